// round 2
// baseline (speedup 1.0000x reference)
#include <cuda_runtime.h>
#include <cuda_bf16.h>
#include <math.h>

// Problem constants
#define SEQ   4096
#define DIM   1280
#define HEADS 16
#define HD    80          // head dim
#define HALF  40          // HD/2 for rotate_half
#define SCALE 0.11180339887498949f  // 80^-0.5

// ---------------------------------------------------------------------------
// Device scratch (no allocations allowed)
// ---------------------------------------------------------------------------
__device__ float g_qkv[(size_t)SEQ * 3 * DIM];     // 62.9 MB
__device__ float g_q[(size_t)HEADS * SEQ * HD];    // 21.0 MB
__device__ float g_k[(size_t)HEADS * SEQ * HD];
__device__ float g_v[(size_t)HEADS * SEQ * HD];
__device__ float g_attn[(size_t)SEQ * DIM];        // 21.0 MB

// ---------------------------------------------------------------------------
// Kernel 1/4: classic 128x128x8 SGEMM with bias epilogue.
// C[M,N] = A[M,K] @ B[K,N] + bias[N]
// Requires M%128==0, N%128==0, K%8==0 (true for all our shapes).
// ---------------------------------------------------------------------------
__global__ __launch_bounds__(256) void sgemm_bias(
    const float* __restrict__ A, const float* __restrict__ B,
    const float* __restrict__ bias, float* __restrict__ C,
    int M, int N, int K)
{
    __shared__ float As[8][128];   // transposed A tile
    __shared__ float Bs[8][128];

    const int tid = threadIdx.x;
    const int bm  = blockIdx.y, bn = blockIdx.x;
    const int tr  = tid >> 4;       // 0..15
    const int tc  = tid & 15;       // 0..15
    const int row0 = bm * 128, col0 = bn * 128;

    // global load assignments
    const int a_row = tid >> 1;            // 0..127
    const int a_col = (tid & 1) * 4;       // 0 or 4
    const int b_row = tid >> 5;            // 0..7
    const int b_col = (tid & 31) * 4;      // 0..124

    float acc[8][8];
#pragma unroll
    for (int i = 0; i < 8; i++)
#pragma unroll
        for (int j = 0; j < 8; j++) acc[i][j] = 0.f;

    for (int k0 = 0; k0 < K; k0 += 8) {
        float4 av = *(const float4*)(A + (size_t)(row0 + a_row) * K + k0 + a_col);
        float4 bv = *(const float4*)(B + (size_t)(k0 + b_row) * N + col0 + b_col);
        As[a_col + 0][a_row] = av.x;
        As[a_col + 1][a_row] = av.y;
        As[a_col + 2][a_row] = av.z;
        As[a_col + 3][a_row] = av.w;
        *(float4*)(&Bs[b_row][b_col]) = bv;
        __syncthreads();

#pragma unroll
        for (int k = 0; k < 8; k++) {
            float a[8], b[8];
            *(float4*)(a)     = *(const float4*)(&As[k][tr * 8]);
            *(float4*)(a + 4) = *(const float4*)(&As[k][tr * 8 + 4]);
            *(float4*)(b)     = *(const float4*)(&Bs[k][tc * 8]);
            *(float4*)(b + 4) = *(const float4*)(&Bs[k][tc * 8 + 4]);
#pragma unroll
            for (int i = 0; i < 8; i++)
#pragma unroll
                for (int j = 0; j < 8; j++)
                    acc[i][j] = fmaf(a[i], b[j], acc[i][j]);
        }
        __syncthreads();
    }

    // epilogue: + bias, float4 stores
#pragma unroll
    for (int i = 0; i < 8; i++) {
        const int r = row0 + tr * 8 + i;
#pragma unroll
        for (int j = 0; j < 8; j += 4) {
            const int c = col0 + tc * 8 + j;
            float4 o;
            o.x = acc[i][j + 0] + bias[c + 0];
            o.y = acc[i][j + 1] + bias[c + 1];
            o.z = acc[i][j + 2] + bias[c + 2];
            o.w = acc[i][j + 3] + bias[c + 3];
            *(float4*)(C + (size_t)r * N + c) = o;
        }
    }
}

// ---------------------------------------------------------------------------
// Kernel 2/4: RoPE + split into head-major Q/K/V: [H][S][D]
// ---------------------------------------------------------------------------
__global__ void rope_split(
    const float* __restrict__ qkv, const float* __restrict__ cosg,
    const float* __restrict__ sing,
    float* __restrict__ Q, float* __restrict__ K, float* __restrict__ V)
{
    int idx = blockIdx.x * blockDim.x + threadIdx.x;  // over SEQ*HEADS*HD
    if (idx >= SEQ * HEADS * HD) return;
    const int d = idx % HD;
    const int h = (idx / HD) % HEADS;
    const int s = idx / (HD * HEADS);

    const float* row = qkv + (size_t)s * 3 * DIM;
    const float c  = cosg[s * HD + d];
    const float sn = sing[s * HD + d];
    const int col  = h * HD + d;

    const int dp   = (d < HALF) ? d + HALF : d - HALF;
    const float sg = (d < HALF) ? -1.f : 1.f;

    const float q  = row[col];
    const float k  = row[DIM + col];
    const float v  = row[2 * DIM + col];
    const float qr = row[h * HD + dp] * sg;
    const float kr = row[DIM + h * HD + dp] * sg;

    const size_t o = ((size_t)h * SEQ + s) * HD + d;
    Q[o] = fmaf(q, c, qr * sn);
    K[o] = fmaf(k, c, kr * sn);
    V[o] = v;
}

// ---------------------------------------------------------------------------
// Kernel 3/4: flash attention, STATIC shared memory (< 48 KB, no attribute
// API calls needed). grid=(SEQ/BM, HEADS), 128 threads.
// BM=64 query rows, BN=32 key rows per iteration. K and V share one smem
// buffer (load K -> S -> load V -> PV), 4 barriers per iteration.
// Thread map: ty=tid>>3 (16), tx=tid&7 (8).
//   S phase : 4x4 microtile, rows r0=ty*4, cols c0=tx*4.
//   PV phase: rows r0..r0+3, head-dims d = tx*10 .. tx*10+9.
// Q/K/V head-major [H][S][HD]. Output written as [S][DIM].
// ---------------------------------------------------------------------------
#define BM 64
#define BN 32
#define DP 81      // padded row stride (81 mod 32 = 17 -> conflict-free)
#define PSTR 36    // P row stride (mult of 4 for float4)

__global__ __launch_bounds__(128) void flash_attn(
    const float* __restrict__ Q, const float* __restrict__ K,
    const float* __restrict__ V, float* __restrict__ O)
{
    __shared__ float Qs[BM * DP];    // 5184 floats
    __shared__ float KVs[BN * DP];   // 2592 floats (K, then V)
    __shared__ float Ps[BM * PSTR];  // 2304 floats
    // total 10080 floats = 40.3 KB static

    const int h   = blockIdx.y;
    const int qb  = blockIdx.x;
    const int tid = threadIdx.x;
    const int ty  = tid >> 3, tx = tid & 7;
    const int r0  = ty * 4, c0 = tx * 4;

    const float* Qg = Q + ((size_t)h * SEQ + (size_t)qb * BM) * HD;
    const float* Kg = K + (size_t)h * SEQ * HD;
    const float* Vg = V + (size_t)h * SEQ * HD;

    // load Q tile: 64*20 float4, 10 per thread
#pragma unroll
    for (int f = tid; f < BM * (HD / 4); f += 128) {
        const int r = f / (HD / 4), c4 = f % (HD / 4);
        float4 v4 = *(const float4*)(Qg + (size_t)r * HD + c4 * 4);
        float* dst = Qs + r * DP + c4 * 4;
        dst[0] = v4.x; dst[1] = v4.y; dst[2] = v4.z; dst[3] = v4.w;
    }

    float m[4], l[4], acc[4][10];
#pragma unroll
    for (int i = 0; i < 4; i++) {
        m[i] = -1e30f; l[i] = 0.f;
#pragma unroll
        for (int dd = 0; dd < 10; dd++) acc[i][dd] = 0.f;
    }
    __syncthreads();

    for (int kb = 0; kb < SEQ / BN; kb++) {
        const float* kg = Kg + (size_t)kb * BN * HD;
        const float* vg = Vg + (size_t)kb * BN * HD;

        // --- load K tile (32*20 float4, 5 per thread) ---
#pragma unroll
        for (int f = tid; f < BN * (HD / 4); f += 128) {
            const int r = f / (HD / 4), c4 = f % (HD / 4);
            float4 k4 = *(const float4*)(kg + (size_t)r * HD + c4 * 4);
            float* kd = KVs + r * DP + c4 * 4;
            kd[0] = k4.x; kd[1] = k4.y; kd[2] = k4.z; kd[3] = k4.w;
        }
        __syncthreads();

        // --- S = Q @ K^T (4x4 microtile) ---
        float s[4][4];
#pragma unroll
        for (int i = 0; i < 4; i++)
#pragma unroll
            for (int j = 0; j < 4; j++) s[i][j] = 0.f;

        for (int d = 0; d < HD; d++) {
            float qv[4], kv[4];
#pragma unroll
            for (int i = 0; i < 4; i++) qv[i] = Qs[(r0 + i) * DP + d];
#pragma unroll
            for (int j = 0; j < 4; j++) kv[j] = KVs[(c0 + j) * DP + d];
#pragma unroll
            for (int i = 0; i < 4; i++)
#pragma unroll
                for (int j = 0; j < 4; j++)
                    s[i][j] = fmaf(qv[i], kv[j], s[i][j]);
        }

        // --- online softmax (reduce over tx = lane bits 0..2) ---
#pragma unroll
        for (int i = 0; i < 4; i++) {
            float mx = -1e30f;
#pragma unroll
            for (int j = 0; j < 4; j++) {
                s[i][j] *= SCALE;
                mx = fmaxf(mx, s[i][j]);
            }
            mx = fmaxf(mx, __shfl_xor_sync(0xffffffffu, mx, 1));
            mx = fmaxf(mx, __shfl_xor_sync(0xffffffffu, mx, 2));
            mx = fmaxf(mx, __shfl_xor_sync(0xffffffffu, mx, 4));

            const float mn = fmaxf(m[i], mx);
            float4 p;
            p.x = __expf(s[i][0] - mn);
            p.y = __expf(s[i][1] - mn);
            p.z = __expf(s[i][2] - mn);
            p.w = __expf(s[i][3] - mn);
            float sum = p.x + p.y + p.z + p.w;
            sum += __shfl_xor_sync(0xffffffffu, sum, 1);
            sum += __shfl_xor_sync(0xffffffffu, sum, 2);
            sum += __shfl_xor_sync(0xffffffffu, sum, 4);

            const float alpha = __expf(m[i] - mn);
            l[i] = l[i] * alpha + sum;
            m[i] = mn;
#pragma unroll
            for (int dd = 0; dd < 10; dd++) acc[i][dd] *= alpha;
            *(float4*)(Ps + (r0 + i) * PSTR + c0) = p;
        }
        __syncthreads();   // S/K reads + P writes complete

        // --- load V tile into shared K/V buffer ---
#pragma unroll
        for (int f = tid; f < BN * (HD / 4); f += 128) {
            const int r = f / (HD / 4), c4 = f % (HD / 4);
            float4 v4 = *(const float4*)(vg + (size_t)r * HD + c4 * 4);
            float* vd = KVs + r * DP + c4 * 4;
            vd[0] = v4.x; vd[1] = v4.y; vd[2] = v4.z; vd[3] = v4.w;
        }
        __syncthreads();

        // --- O += P @ V : 4 rows x 10 head-dims per thread ---
        const int dcol = tx * 10;
#pragma unroll
        for (int n = 0; n < BN; n += 4) {
            float4 pr[4];
#pragma unroll
            for (int i = 0; i < 4; i++)
                pr[i] = *(const float4*)(Ps + (r0 + i) * PSTR + n);
#pragma unroll
            for (int nn = 0; nn < 4; nn++) {
                float vv[10];
#pragma unroll
                for (int dd = 0; dd < 10; dd++)
                    vv[dd] = KVs[(n + nn) * DP + dcol + dd];
                const float p0 = ((const float*)&pr[0])[nn];
                const float p1 = ((const float*)&pr[1])[nn];
                const float p2 = ((const float*)&pr[2])[nn];
                const float p3 = ((const float*)&pr[3])[nn];
#pragma unroll
                for (int dd = 0; dd < 10; dd++) {
                    acc[0][dd] = fmaf(p0, vv[dd], acc[0][dd]);
                    acc[1][dd] = fmaf(p1, vv[dd], acc[1][dd]);
                    acc[2][dd] = fmaf(p2, vv[dd], acc[2][dd]);
                    acc[3][dd] = fmaf(p3, vv[dd], acc[3][dd]);
                }
            }
        }
        __syncthreads();   // PV done before next K load overwrites KVs
    }

    // epilogue: normalize and scatter to [S][DIM]
#pragma unroll
    for (int i = 0; i < 4; i++) {
        const float inv = 1.f / l[i];
        const int row = qb * BM + r0 + i;
#pragma unroll
        for (int dd = 0; dd < 10; dd++) {
            const int d = tx * 10 + dd;
            O[(size_t)row * DIM + h * HD + d] = acc[i][dd] * inv;
        }
    }
}

// ---------------------------------------------------------------------------
// Launch (kernel launches only — no attribute calls, no allocs, no syncs)
// ---------------------------------------------------------------------------
extern "C" void kernel_launch(void* const* d_in, const int* in_sizes, int n_in,
                              void* d_out, int out_size)
{
    const float* x      = (const float*)d_in[0];
    const float* cosg   = (const float*)d_in[1];
    const float* sing   = (const float*)d_in[2];
    const float* qkv_w  = (const float*)d_in[3];
    const float* qkv_b  = (const float*)d_in[4];
    const float* proj_w = (const float*)d_in[5];
    const float* proj_b = (const float*)d_in[6];
    float* out = (float*)d_out;

    float *qkv, *q, *k, *v, *attn;
    cudaGetSymbolAddress((void**)&qkv,  g_qkv);
    cudaGetSymbolAddress((void**)&q,    g_q);
    cudaGetSymbolAddress((void**)&k,    g_k);
    cudaGetSymbolAddress((void**)&v,    g_v);
    cudaGetSymbolAddress((void**)&attn, g_attn);

    // 1. QKV GEMM: [4096,1280] @ [1280,3840] + bias
    sgemm_bias<<<dim3(3 * DIM / 128, SEQ / 128), 256>>>(
        x, qkv_w, qkv_b, qkv, SEQ, 3 * DIM, DIM);

    // 2. RoPE + head-major split
    {
        const int n = SEQ * HEADS * HD;
        rope_split<<<(n + 255) / 256, 256>>>(qkv, cosg, sing, q, k, v);
    }

    // 3. Flash attention (static smem, 40.3 KB)
    flash_attn<<<dim3(SEQ / BM, HEADS), 128>>>(q, k, v, attn);

    // 4. Output projection: [4096,1280] @ [1280,1280] + bias
    sgemm_bias<<<dim3(DIM / 128, SEQ / 128), 256>>>(
        attn, proj_w, proj_b, out, SEQ, DIM, DIM);
}